// round 2
// baseline (speedup 1.0000x reference)
#include <cuda_runtime.h>

// loss = ALPHA*mean(G) + (1-ALPHA)*mse
//   mse     = sum_{t>0}(t-p)^2 / max(count,1)
//   mean(G) = (1/N) * sum over 4 corners (3x3) of (t-p)*wr[i]*wr[j]
//   (double reflect-101 conv of zero-sum composed kernel => interior weights
//    cancel; boundary row weights wr = [-0.75,-1,-0.25, 0..0, 0.25,1,0.75])
//
// Single fused kernel: per-block partials + self-resetting ticket; the last
// block to arrive folds partials (fp64), adds the corner term, writes out.

#define ALPHA 0.2
#define H_DIM 4096
#define W_DIM 4096
#define GRID  2048
#define NTHR  256

__device__ float2       g_partials[GRID];
__device__ unsigned int g_ticket = 0;   // atomicInc wraps back to 0 -> no init needed

__global__ void __launch_bounds__(NTHR) el_fused_kernel(
    const float4* __restrict__ pred4,
    const float4* __restrict__ targ4,
    const float*  __restrict__ pred,
    const float*  __restrict__ targ,
    float* __restrict__ out,
    int n4)
{
    float s = 0.0f;
    float c = 0.0f;
    const int stride = GRID * NTHR;
    for (int i = blockIdx.x * NTHR + threadIdx.x; i < n4; i += stride) {
        float4 t = __ldg(targ4 + i);
        float4 p = __ldg(pred4 + i);
        if (t.x > 0.0f) { float d = t.x - p.x; s = fmaf(d, d, s); c += 1.0f; }
        if (t.y > 0.0f) { float d = t.y - p.y; s = fmaf(d, d, s); c += 1.0f; }
        if (t.z > 0.0f) { float d = t.z - p.z; s = fmaf(d, d, s); c += 1.0f; }
        if (t.w > 0.0f) { float d = t.w - p.w; s = fmaf(d, d, s); c += 1.0f; }
    }

    // intra-block reduce (warp shuffles + smem)
    #pragma unroll
    for (int o = 16; o > 0; o >>= 1) {
        s += __shfl_down_sync(0xFFFFFFFFu, s, o);
        c += __shfl_down_sync(0xFFFFFFFFu, c, o);
    }
    __shared__ float ss[8], sc[8];
    int lane = threadIdx.x & 31;
    int wid  = threadIdx.x >> 5;
    if (lane == 0) { ss[wid] = s; sc[wid] = c; }
    __syncthreads();
    if (wid == 0) {
        s = (lane < (NTHR >> 5)) ? ss[lane] : 0.0f;
        c = (lane < (NTHR >> 5)) ? sc[lane] : 0.0f;
        #pragma unroll
        for (int o = 4; o > 0; o >>= 1) {
            s += __shfl_down_sync(0xFFFFFFFFu, s, o);
            c += __shfl_down_sync(0xFFFFFFFFu, c, o);
        }
    }

    // publish partial, take ticket (self-resetting)
    __shared__ bool is_last;
    if (threadIdx.x == 0) {
        g_partials[blockIdx.x] = make_float2(s, c);
        __threadfence();
        unsigned int ticket = atomicInc(&g_ticket, GRID - 1);
        is_last = (ticket == GRID - 1);
    }
    __syncthreads();
    if (!is_last) return;

    // ---- last block: fold partials in fp64 ----
    double ds = 0.0, dc = 0.0;
    for (int i = threadIdx.x; i < GRID; i += NTHR) {
        // volatile read: partials were written by other blocks (fenced)
        volatile float2* vp = (volatile float2*)&g_partials[i];
        float2 v; v.x = vp->x; v.y = vp->y;
        ds += (double)v.x;
        dc += (double)v.y;
    }
    #pragma unroll
    for (int o = 16; o > 0; o >>= 1) {
        ds += __shfl_down_sync(0xFFFFFFFFu, ds, o);
        dc += __shfl_down_sync(0xFFFFFFFFu, dc, o);
    }
    __shared__ double dss[8], dcc[8];
    if (lane == 0) { dss[wid] = ds; dcc[wid] = dc; }
    __syncthreads();
    if (wid == 0) {
        ds = (lane < (NTHR >> 5)) ? dss[lane] : 0.0;
        dc = (lane < (NTHR >> 5)) ? dcc[lane] : 0.0;
        #pragma unroll
        for (int o = 4; o > 0; o >>= 1) {
            ds += __shfl_down_sync(0xFFFFFFFFu, ds, o);
            dc += __shfl_down_sync(0xFFFFFFFFu, dc, o);
        }
        if (lane == 0) {
            // 36-pixel corner term of the collapsed edge branch
            const int    idx[6] = {0, 1, 2, H_DIM - 3, H_DIM - 2, H_DIM - 1};
            const double w[6]   = {-0.75, -1.0, -0.25, 0.25, 1.0, 0.75};
            double corner = 0.0;
            #pragma unroll
            for (int a = 0; a < 6; a++) {
                #pragma unroll
                for (int b = 0; b < 6; b++) {
                    long off = (long)idx[a] * W_DIM + idx[b];
                    double d = (double)__ldg(targ + off) - (double)__ldg(pred + off);
                    corner += d * w[a] * w[b];
                }
            }
            double cnt = (dc < 1.0) ? 1.0 : dc;
            double mse = ds / cnt;
            double N   = (double)H_DIM * (double)W_DIM;
            out[0] = (float)(ALPHA * (corner / N) + (1.0 - ALPHA) * mse);
        }
    }
}

extern "C" void kernel_launch(void* const* d_in, const int* in_sizes, int n_in,
                              void* d_out, int out_size) {
    const float* pred = (const float*)d_in[0];
    const float* targ = (const float*)d_in[1];
    float* out = (float*)d_out;
    int n4 = in_sizes[0] >> 2;

    el_fused_kernel<<<GRID, NTHR>>>((const float4*)pred, (const float4*)targ,
                                    pred, targ, out, n4);
}

// round 3
// speedup vs baseline: 1.1292x; 1.1292x over previous
#include <cuda_runtime.h>

// loss = ALPHA*mean(G) + (1-ALPHA)*mse
//   mse     = sum_{t>0}(t-p)^2 / max(count,1)
//   mean(G) = (1/N) * sum over 4 corners (3x3) of (t-p)*wr[i]*wr[j]
//   (double reflect-101 conv of the zero-sum composed kernel collapses to a
//    36-pixel corner term; wr = [-0.75,-1,-0.25, 0..0, 0.25,1,0.75])
//
// Single fused kernel. Main loop batches 8 independent LDG.128s per thread
// (MLP_p1=8) to saturate HBM; self-resetting ticket + last-block finalize.

#define ALPHA 0.2
#define H_DIM 4096
#define W_DIM 4096
#define GRID  1184   // 148 SMs * 8
#define NTHR  256

__device__ float2       g_partials[GRID];
__device__ unsigned int g_ticket = 0;   // atomicInc wraps to 0 -> no init kernel

__device__ __forceinline__ void acc4(const float4 t, const float4 p,
                                     float& s, float& c) {
    if (t.x > 0.0f) { float d = t.x - p.x; s = fmaf(d, d, s); c += 1.0f; }
    if (t.y > 0.0f) { float d = t.y - p.y; s = fmaf(d, d, s); c += 1.0f; }
    if (t.z > 0.0f) { float d = t.z - p.z; s = fmaf(d, d, s); c += 1.0f; }
    if (t.w > 0.0f) { float d = t.w - p.w; s = fmaf(d, d, s); c += 1.0f; }
}

__global__ void __launch_bounds__(NTHR) el_fused_kernel(
    const float4* __restrict__ pred4,
    const float4* __restrict__ targ4,
    const float*  __restrict__ pred,
    const float*  __restrict__ targ,
    float* __restrict__ out,
    int n4)
{
    float s = 0.0f;
    float c = 0.0f;
    const int stride = GRID * NTHR;
    int i = blockIdx.x * NTHR + threadIdx.x;

    // Batched main loop: 8 independent 16B loads in flight per thread.
    for (; i < n4 - 3 * stride; i += 4 * stride) {
        float4 t0 = targ4[i];
        float4 t1 = targ4[i +     stride];
        float4 t2 = targ4[i + 2 * stride];
        float4 t3 = targ4[i + 3 * stride];
        float4 p0 = pred4[i];
        float4 p1 = pred4[i +     stride];
        float4 p2 = pred4[i + 2 * stride];
        float4 p3 = pred4[i + 3 * stride];
        acc4(t0, p0, s, c);
        acc4(t1, p1, s, c);
        acc4(t2, p2, s, c);
        acc4(t3, p3, s, c);
    }
    // Remainder (1-2 iterations per thread, warp-uniform).
    for (; i < n4; i += stride) {
        float4 t = targ4[i];
        float4 p = pred4[i];
        acc4(t, p, s, c);
    }

    // intra-block reduce
    #pragma unroll
    for (int o = 16; o > 0; o >>= 1) {
        s += __shfl_down_sync(0xFFFFFFFFu, s, o);
        c += __shfl_down_sync(0xFFFFFFFFu, c, o);
    }
    __shared__ float ss[8], sc[8];
    int lane = threadIdx.x & 31;
    int wid  = threadIdx.x >> 5;
    if (lane == 0) { ss[wid] = s; sc[wid] = c; }
    __syncthreads();
    if (wid == 0) {
        s = (lane < (NTHR >> 5)) ? ss[lane] : 0.0f;
        c = (lane < (NTHR >> 5)) ? sc[lane] : 0.0f;
        #pragma unroll
        for (int o = 4; o > 0; o >>= 1) {
            s += __shfl_down_sync(0xFFFFFFFFu, s, o);
            c += __shfl_down_sync(0xFFFFFFFFu, c, o);
        }
    }

    // publish partial, take self-resetting ticket
    __shared__ bool is_last;
    if (threadIdx.x == 0) {
        g_partials[blockIdx.x] = make_float2(s, c);
        __threadfence();
        unsigned int ticket = atomicInc(&g_ticket, GRID - 1);
        is_last = (ticket == GRID - 1);
    }
    __syncthreads();
    if (!is_last) return;

    // ---- last block: fold partials in fp64, finalize ----
    double ds = 0.0, dc = 0.0;
    for (int k = threadIdx.x; k < GRID; k += NTHR) {
        volatile float2* vp = (volatile float2*)&g_partials[k];
        ds += (double)vp->x;
        dc += (double)vp->y;
    }
    #pragma unroll
    for (int o = 16; o > 0; o >>= 1) {
        ds += __shfl_down_sync(0xFFFFFFFFu, ds, o);
        dc += __shfl_down_sync(0xFFFFFFFFu, dc, o);
    }
    __shared__ double dss[8], dcc[8];
    if (lane == 0) { dss[wid] = ds; dcc[wid] = dc; }
    __syncthreads();
    if (wid == 0) {
        ds = (lane < (NTHR >> 5)) ? dss[lane] : 0.0;
        dc = (lane < (NTHR >> 5)) ? dcc[lane] : 0.0;
        #pragma unroll
        for (int o = 4; o > 0; o >>= 1) {
            ds += __shfl_down_sync(0xFFFFFFFFu, ds, o);
            dc += __shfl_down_sync(0xFFFFFFFFu, dc, o);
        }
        if (lane == 0) {
            const int    idx[6] = {0, 1, 2, H_DIM - 3, H_DIM - 2, H_DIM - 1};
            const double w[6]   = {-0.75, -1.0, -0.25, 0.25, 1.0, 0.75};
            double corner = 0.0;
            #pragma unroll
            for (int a = 0; a < 6; a++) {
                #pragma unroll
                for (int b = 0; b < 6; b++) {
                    long off = (long)idx[a] * W_DIM + idx[b];
                    double d = (double)__ldg(targ + off) - (double)__ldg(pred + off);
                    corner += d * w[a] * w[b];
                }
            }
            double cnt = (dc < 1.0) ? 1.0 : dc;
            double mse = ds / cnt;
            double N   = (double)H_DIM * (double)W_DIM;
            out[0] = (float)(ALPHA * (corner / N) + (1.0 - ALPHA) * mse);
        }
    }
}

extern "C" void kernel_launch(void* const* d_in, const int* in_sizes, int n_in,
                              void* d_out, int out_size) {
    const float* pred = (const float*)d_in[0];
    const float* targ = (const float*)d_in[1];
    float* out = (float*)d_out;
    int n4 = in_sizes[0] >> 2;

    el_fused_kernel<<<GRID, NTHR>>>((const float4*)pred, (const float4*)targ,
                                    pred, targ, out, n4);
}

// round 4
// speedup vs baseline: 1.1303x; 1.0009x over previous
#include <cuda_runtime.h>

// loss = ALPHA*mean(G) + (1-ALPHA)*mse
//   mse     = sum_{t>0}(t-p)^2 / max(count,1)
//   mean(G) = (1/N) * 36-pixel corner term (double reflect-101 conv of the
//             zero-sum composed kernel collapses; wr = [-.75,-1,-.25,0..0,.25,1,.75])
//
// Single fused kernel. __launch_bounds__(256,4) grants 64 regs/thread so the
// 8 independent LDG.128s per iteration are genuinely front-batched in SASS.

#define ALPHA 0.2
#define H_DIM 4096
#define W_DIM 4096
#define GRID  592    // 148 SMs * 4 CTAs -> exactly one wave
#define NTHR  256

__device__ float2       g_partials[GRID];
__device__ unsigned int g_ticket = 0;   // atomicInc wraps to 0 -> no init kernel

__device__ __forceinline__ void acc4(const float4 t, const float4 p,
                                     float& s, float& c) {
    if (t.x > 0.0f) { float d = t.x - p.x; s = fmaf(d, d, s); c += 1.0f; }
    if (t.y > 0.0f) { float d = t.y - p.y; s = fmaf(d, d, s); c += 1.0f; }
    if (t.z > 0.0f) { float d = t.z - p.z; s = fmaf(d, d, s); c += 1.0f; }
    if (t.w > 0.0f) { float d = t.w - p.w; s = fmaf(d, d, s); c += 1.0f; }
}

__global__ void __launch_bounds__(NTHR, 4) el_fused_kernel(
    const float4* __restrict__ pred4,
    const float4* __restrict__ targ4,
    const float*  __restrict__ pred,
    const float*  __restrict__ targ,
    float* __restrict__ out,
    int n4)
{
    float s = 0.0f;
    float c = 0.0f;
    const int stride = GRID * NTHR;
    int i = blockIdx.x * NTHR + threadIdx.x;

    // Main loop: 8 independent 16B streaming loads in flight per thread.
    #pragma unroll 1
    for (; i + 3 * stride < n4; i += 4 * stride) {
        float4 t0 = __ldcs(targ4 + i);
        float4 t1 = __ldcs(targ4 + i +     stride);
        float4 t2 = __ldcs(targ4 + i + 2 * stride);
        float4 t3 = __ldcs(targ4 + i + 3 * stride);
        float4 p0 = __ldcs(pred4 + i);
        float4 p1 = __ldcs(pred4 + i +     stride);
        float4 p2 = __ldcs(pred4 + i + 2 * stride);
        float4 p3 = __ldcs(pred4 + i + 3 * stride);
        acc4(t0, p0, s, c);
        acc4(t1, p1, s, c);
        acc4(t2, p2, s, c);
        acc4(t3, p3, s, c);
    }
    #pragma unroll 1
    for (; i < n4; i += stride) {
        float4 t = __ldcs(targ4 + i);
        float4 p = __ldcs(pred4 + i);
        acc4(t, p, s, c);
    }

    // intra-block reduce
    #pragma unroll
    for (int o = 16; o > 0; o >>= 1) {
        s += __shfl_down_sync(0xFFFFFFFFu, s, o);
        c += __shfl_down_sync(0xFFFFFFFFu, c, o);
    }
    __shared__ float ss[8], sc[8];
    int lane = threadIdx.x & 31;
    int wid  = threadIdx.x >> 5;
    if (lane == 0) { ss[wid] = s; sc[wid] = c; }
    __syncthreads();
    if (wid == 0) {
        s = (lane < (NTHR >> 5)) ? ss[lane] : 0.0f;
        c = (lane < (NTHR >> 5)) ? sc[lane] : 0.0f;
        #pragma unroll
        for (int o = 4; o > 0; o >>= 1) {
            s += __shfl_down_sync(0xFFFFFFFFu, s, o);
            c += __shfl_down_sync(0xFFFFFFFFu, c, o);
        }
    }

    // publish partial, take self-resetting ticket
    __shared__ bool is_last;
    if (threadIdx.x == 0) {
        g_partials[blockIdx.x] = make_float2(s, c);
        __threadfence();
        unsigned int ticket = atomicInc(&g_ticket, GRID - 1);
        is_last = (ticket == GRID - 1);
    }
    __syncthreads();
    if (!is_last) return;

    // ---- last block: fold partials in fp64, finalize ----
    double ds = 0.0, dc = 0.0;
    for (int k = threadIdx.x; k < GRID; k += NTHR) {
        volatile float2* vp = (volatile float2*)&g_partials[k];
        ds += (double)vp->x;
        dc += (double)vp->y;
    }
    #pragma unroll
    for (int o = 16; o > 0; o >>= 1) {
        ds += __shfl_down_sync(0xFFFFFFFFu, ds, o);
        dc += __shfl_down_sync(0xFFFFFFFFu, dc, o);
    }
    __shared__ double dss[8], dcc[8];
    if (lane == 0) { dss[wid] = ds; dcc[wid] = dc; }
    __syncthreads();
    if (wid == 0) {
        ds = (lane < (NTHR >> 5)) ? dss[lane] : 0.0;
        dc = (lane < (NTHR >> 5)) ? dcc[lane] : 0.0;
        #pragma unroll
        for (int o = 4; o > 0; o >>= 1) {
            ds += __shfl_down_sync(0xFFFFFFFFu, ds, o);
            dc += __shfl_down_sync(0xFFFFFFFFu, dc, o);
        }
        if (lane == 0) {
            const int    idx[6] = {0, 1, 2, H_DIM - 3, H_DIM - 2, H_DIM - 1};
            const double w[6]   = {-0.75, -1.0, -0.25, 0.25, 1.0, 0.75};
            double corner = 0.0;
            #pragma unroll
            for (int a = 0; a < 6; a++) {
                #pragma unroll
                for (int b = 0; b < 6; b++) {
                    long off = (long)idx[a] * W_DIM + idx[b];
                    double d = (double)__ldg(targ + off) - (double)__ldg(pred + off);
                    corner += d * w[a] * w[b];
                }
            }
            double cnt = (dc < 1.0) ? 1.0 : dc;
            double mse = ds / cnt;
            double N   = (double)H_DIM * (double)W_DIM;
            out[0] = (float)(ALPHA * (corner / N) + (1.0 - ALPHA) * mse);
        }
    }
}

extern "C" void kernel_launch(void* const* d_in, const int* in_sizes, int n_in,
                              void* d_out, int out_size) {
    const float* pred = (const float*)d_in[0];
    const float* targ = (const float*)d_in[1];
    float* out = (float*)d_out;
    int n4 = in_sizes[0] >> 2;

    el_fused_kernel<<<GRID, NTHR>>>((const float4*)pred, (const float4*)targ,
                                    pred, targ, out, n4);
}